// round 1
// baseline (speedup 1.0000x reference)
#include <cuda_runtime.h>
#include <math.h>

// Problem constants
#define Bz 64
#define Tz 512
#define Nz 1024
#define Hz 1024
#define G3 3072                      // 3*H
#define Mz (Bz * Tz)                 // 32768

// Scratch for the precomputed input projection xW = x @ W_ih^T + b_ih : [B*T, 3H]
// (402 MB; __device__ global is the sanctioned allocation-free scratch.)
__device__ float g_xw[(size_t)Mz * G3];

// ---------------------------------------------------------------------------
// Kernel 1: big SGEMM  g_xw[m, n] = sum_k x[m,k] * W_ih[n,k] + b_ih[n]
// 128x128 tile, BK=16, 256 threads, 8x8 register micro-tile.
// ---------------------------------------------------------------------------
__global__ __launch_bounds__(256) void gemm_xw(const float* __restrict__ x,
                                               const float* __restrict__ W,
                                               const float* __restrict__ bias) {
    __shared__ __align__(16) float As[16][132];   // [k][m], padded
    __shared__ __align__(16) float Ws[16][132];   // [k][n], padded

    const int tid = threadIdx.x;
    const int mb = blockIdx.y * 128;
    const int nb = blockIdx.x * 128;
    const int tn = tid & 15;          // 0..15 -> 8 output cols each
    const int tm = tid >> 4;          // 0..15 -> 8 output rows each

    float acc[8][8];
#pragma unroll
    for (int i = 0; i < 8; i++)
#pragma unroll
        for (int j = 0; j < 8; j++) acc[i][j] = 0.0f;

    for (int kt = 0; kt < Nz; kt += 16) {
        // Load 128x16 tiles of A (x) and B (W_ih), stored transposed into smem.
#pragma unroll
        for (int i = 0; i < 2; i++) {
            int idx = tid + i * 256;          // 0..511 (float4 units)
            int row = idx >> 2;               // 0..127
            int kc  = (idx & 3) * 4;          // 0,4,8,12
            float4 va = *(const float4*)&x[(size_t)(mb + row) * Nz + kt + kc];
            As[kc + 0][row] = va.x; As[kc + 1][row] = va.y;
            As[kc + 2][row] = va.z; As[kc + 3][row] = va.w;
            float4 vw = *(const float4*)&W[(size_t)(nb + row) * Nz + kt + kc];
            Ws[kc + 0][row] = vw.x; Ws[kc + 1][row] = vw.y;
            Ws[kc + 2][row] = vw.z; Ws[kc + 3][row] = vw.w;
        }
        __syncthreads();

#pragma unroll
        for (int kk = 0; kk < 16; kk++) {
            float a[8], w[8];
#pragma unroll
            for (int i = 0; i < 8; i++) a[i] = As[kk][tm * 8 + i];
#pragma unroll
            for (int j = 0; j < 8; j++) w[j] = Ws[kk][tn * 8 + j];
#pragma unroll
            for (int i = 0; i < 8; i++)
#pragma unroll
                for (int j = 0; j < 8; j++) acc[i][j] = fmaf(a[i], w[j], acc[i][j]);
        }
        __syncthreads();
    }

    // Epilogue: add bias, store.
    float bv[8];
#pragma unroll
    for (int j = 0; j < 8; j++) bv[j] = bias[nb + tn * 8 + j];
#pragma unroll
    for (int i = 0; i < 8; i++) {
        size_t base = (size_t)(mb + tm * 8 + i) * G3 + nb + tn * 8;
        float4 v0 = make_float4(acc[i][0] + bv[0], acc[i][1] + bv[1],
                                acc[i][2] + bv[2], acc[i][3] + bv[3]);
        float4 v1 = make_float4(acc[i][4] + bv[4], acc[i][5] + bv[5],
                                acc[i][6] + bv[6], acc[i][7] + bv[7]);
        *(float4*)&g_xw[base + 0] = v0;
        *(float4*)&g_xw[base + 4] = v1;
    }
}

// ---------------------------------------------------------------------------
// Kernel 2: one GRU step (launched 512x).
// Grid: 128 CTAs (8 h-columns each), 256 threads.
// Each thread: 2 batches x 1 column x 3 gates = 6 dot-product accumulators.
// h(t-1) is read from d_out (written by the previous launch); t==0 -> zeros.
// ---------------------------------------------------------------------------
__global__ __launch_bounds__(256) void gru_step(const float* __restrict__ Whh,
                                                const float* __restrict__ bhh,
                                                const float* __restrict__ mix,
                                                float* __restrict__ out,
                                                int t) {
    __shared__ __align__(16) float hs[64][36];   // h tile, padded (36*4B rows)
    __shared__ __align__(16) float ws[24][36];   // W rows: [gate*8 + jg][k]

    const int tid = threadIdx.x;
    const int jb = blockIdx.x * 8;
    const int jg = tid & 7;           // column within tile
    const int bg = tid >> 3;          // 0..31 -> batches 2*bg, 2*bg+1
    const int j  = jb + jg;
    const int b0 = bg * 2;
    const int b1 = b0 + 1;
    const size_t TH = (size_t)Tz * Hz;

    float ar0 = 0.f, az0 = 0.f, an0 = 0.f;
    float ar1 = 0.f, az1 = 0.f, an1 = 0.f;

    for (int kb = 0; kb < Hz; kb += 32) {
        // Load h(t-1) tile: 64 batches x 32 k  (512 float4 / 256 threads)
#pragma unroll
        for (int i = 0; i < 2; i++) {
            int idx = tid + i * 256;
            int row = idx >> 3;              // batch 0..63
            int kc  = (idx & 7) * 4;         // 0..28
            float4 v;
            if (t == 0) v = make_float4(0.f, 0.f, 0.f, 0.f);
            else v = *(const float4*)&out[(size_t)row * TH + (size_t)(t - 1) * Hz + kb + kc];
            *(float4*)&hs[row][kc] = v;
        }
        // Load W_hh tile: 24 rows (r/z/n for 8 columns) x 32 k
        if (tid < 192) {
            int row = tid >> 3;              // 0..23
            int kc  = (tid & 7) * 4;
            int g   = row >> 3;              // gate 0..2
            int jj  = row & 7;
            float4 v = *(const float4*)&Whh[(size_t)(g * Hz + jb + jj) * Hz + kb + kc];
            *(float4*)&ws[row][kc] = v;
        }
        __syncthreads();

#pragma unroll
        for (int k4 = 0; k4 < 8; k4++) {
            float4 ha = *(const float4*)&hs[b0][k4 * 4];
            float4 hb = *(const float4*)&hs[b1][k4 * 4];
            float4 wr = *(const float4*)&ws[jg][k4 * 4];
            float4 wz = *(const float4*)&ws[8 + jg][k4 * 4];
            float4 wn = *(const float4*)&ws[16 + jg][k4 * 4];

            ar0 = fmaf(ha.x, wr.x, ar0); ar0 = fmaf(ha.y, wr.y, ar0);
            ar0 = fmaf(ha.z, wr.z, ar0); ar0 = fmaf(ha.w, wr.w, ar0);
            az0 = fmaf(ha.x, wz.x, az0); az0 = fmaf(ha.y, wz.y, az0);
            az0 = fmaf(ha.z, wz.z, az0); az0 = fmaf(ha.w, wz.w, az0);
            an0 = fmaf(ha.x, wn.x, an0); an0 = fmaf(ha.y, wn.y, an0);
            an0 = fmaf(ha.z, wn.z, an0); an0 = fmaf(ha.w, wn.w, an0);

            ar1 = fmaf(hb.x, wr.x, ar1); ar1 = fmaf(hb.y, wr.y, ar1);
            ar1 = fmaf(hb.z, wr.z, ar1); ar1 = fmaf(hb.w, wr.w, ar1);
            az1 = fmaf(hb.x, wz.x, az1); az1 = fmaf(hb.y, wz.y, az1);
            az1 = fmaf(hb.z, wz.z, az1); az1 = fmaf(hb.w, wz.w, az1);
            an1 = fmaf(hb.x, wn.x, an1); an1 = fmaf(hb.y, wn.y, an1);
            an1 = fmaf(hb.z, wn.z, an1); an1 = fmaf(hb.w, wn.w, an1);
        }
        __syncthreads();
    }

    const float bhr = bhh[j];
    const float bhz = bhh[Hz + j];
    const float bhn = bhh[2 * Hz + j];

#pragma unroll
    for (int s = 0; s < 2; s++) {
        int b = (s == 0) ? b0 : b1;
        float hr = ((s == 0) ? ar0 : ar1) + bhr;
        float hz = ((s == 0) ? az0 : az1) + bhz;
        float hn = ((s == 0) ? an0 : an1) + bhn;

        size_t xbase = ((size_t)b * Tz + t) * G3;
        float xr = g_xw[xbase + j];
        float xz = g_xw[xbase + Hz + j];
        float xn = g_xw[xbase + 2 * Hz + j];

        float r = 1.0f / (1.0f + expf(-(xr + hr)));
        float z = 1.0f / (1.0f + expf(-(xz + hz)));
        float n = tanhf(xn + r * hn);

        float hp = (t == 0) ? 0.0f
                            : out[(size_t)b * TH + (size_t)(t - 1) * Hz + j];
        float hnew = (1.0f - z) * n + z * hp;
        float m = mix[b * Tz + t];
        float hm = hnew * m + hp * (1.0f - m);

        out[(size_t)b * TH + (size_t)t * Hz + j] = hm;
        if (t == Tz - 1) {
            // second output 'o' = final carry, appended after h
            out[(size_t)Bz * TH + (size_t)b * Hz + j] = hm;
        }
    }
}

// ---------------------------------------------------------------------------
extern "C" void kernel_launch(void* const* d_in, const int* in_sizes, int n_in,
                              void* d_out, int out_size) {
    const float* x   = (const float*)d_in[0];
    const float* mix = (const float*)d_in[1];
    const float* Wih = (const float*)d_in[2];
    const float* Whh = (const float*)d_in[3];
    const float* bih = (const float*)d_in[4];
    const float* bhh = (const float*)d_in[5];
    float* out = (float*)d_out;

    dim3 ggrid(G3 / 128, Mz / 128);   // 24 x 256
    gemm_xw<<<ggrid, 256>>>(x, Wih, bih);

    for (int t = 0; t < Tz; t++) {
        gru_step<<<Hz / 8, 256>>>(Whh, bhh, mix, out, t);
    }
}

// round 5
// speedup vs baseline: 1.2649x; 1.2649x over previous
#include <cuda_runtime.h>
#include <cuda_pipeline.h>
#include <math.h>

// Problem constants
#define Bz 64
#define Tz 512
#define Nz 1024
#define Hz 1024
#define G3 3072
#define Mz (Bz * Tz)

// Scratch: input projection xW = x @ W_ih^T + b_ih : [B*T, 3H]
__device__ float g_xw[(size_t)Mz * G3];

// Packed fp32x2 FMA (sm_103a FFMA2) — identical rounding to two fmaf's.
__device__ __forceinline__ unsigned long long ffma2(unsigned long long a,
                                                    unsigned long long b,
                                                    unsigned long long c) {
    unsigned long long d;
    asm("fma.rn.f32x2 %0, %1, %2, %3;" : "=l"(d) : "l"(a), "l"(b), "l"(c));
    return d;
}
__device__ __forceinline__ float unpack_sum(unsigned long long v) {
    float lo = __uint_as_float((unsigned)(v & 0xffffffffULL));
    float hi = __uint_as_float((unsigned)(v >> 32));
    return lo + hi;
}

// ---------------------------------------------------------------------------
// Kernel 1: g_xw[m,n] = sum_k x[m,k]*W_ih[n,k] + b_ih[n]
// 128(m) x 64(n) tile, BK=32, 256 threads, 8x4 strided micro-tile, FFMA2 over
// k-pairs, cp.async double-buffered, XOR-swizzled smem (128B pitch).
// ---------------------------------------------------------------------------
__global__ __launch_bounds__(256, 2) void gemm_xw(const float* __restrict__ x,
                                                  const float* __restrict__ W,
                                                  const float* __restrict__ bias) {
    // pitch = 16 doubles (128B) per row; 8 x 16B chunks per row, XOR-swizzled.
    __shared__ __align__(16) double As[2][128 * 16];
    __shared__ __align__(16) double Bs[2][64 * 16];

    const int tid = threadIdx.x;
    const int mb = blockIdx.y * 128;
    const int nb = blockIdx.x * 64;
    const int tn = tid & 15;
    const int tm = tid >> 4;

    unsigned long long acc[8][4];
#pragma unroll
    for (int i = 0; i < 8; i++)
#pragma unroll
        for (int j = 0; j < 4; j++) acc[i][j] = 0ULL;

    // async tile loader: BK=32 floats per row slice
    auto load_tile = [&](int kt, int buf) {
#pragma unroll
        for (int c = 0; c < 4; c++) {               // As: 1024 x 16B chunks
            int id = tid + 256 * c;
            int row = id >> 3;
            int off = id & 7;
            int swz = (row ^ (row >> 3)) & 7;
            __pipeline_memcpy_async(
                (char*)&As[buf][row * 16] + ((off ^ swz) * 16),
                &x[(size_t)(mb + row) * Nz + kt + off * 4], 16);
        }
#pragma unroll
        for (int c = 0; c < 2; c++) {               // Bs: 512 x 16B chunks
            int id = tid + 256 * c;
            int row = id >> 3;
            int off = id & 7;
            int swz = (row ^ (row >> 3)) & 7;
            __pipeline_memcpy_async(
                (char*)&Bs[buf][row * 16] + ((off ^ swz) * 16),
                &W[(size_t)(nb + row) * Nz + kt + off * 4], 16);
        }
        __pipeline_commit();
    };

    load_tile(0, 0);
    load_tile(32, 1);

    for (int it = 0; it < 32; ++it) {
        if (it < 30) __pipeline_wait_prior(1);
        else         __pipeline_wait_prior(0);
        __syncthreads();
        const double* A = As[it & 1];
        const double* B = Bs[it & 1];
#pragma unroll
        for (int kp2 = 0; kp2 < 8; ++kp2) {
            ulonglong2 av[8], bv[4];
#pragma unroll
            for (int i = 0; i < 8; i++) {
                int m = tm + 16 * i;
                int pos = kp2 ^ ((m ^ (m >> 3)) & 7);
                av[i] = *(const ulonglong2*)&A[m * 16 + pos * 2];
            }
#pragma unroll
            for (int j = 0; j < 4; j++) {
                int n = tn + 16 * j;
                int pos = kp2 ^ ((n ^ (n >> 3)) & 7);
                bv[j] = *(const ulonglong2*)&B[n * 16 + pos * 2];
            }
#pragma unroll
            for (int i = 0; i < 8; i++)
#pragma unroll
                for (int j = 0; j < 4; j++) {
                    acc[i][j] = ffma2(av[i].x, bv[j].x, acc[i][j]);
                    acc[i][j] = ffma2(av[i].y, bv[j].y, acc[i][j]);
                }
        }
        __syncthreads();
        if (it + 2 < 32) load_tile((it + 2) * 32, it & 1);
    }

    float bvv[4];
#pragma unroll
    for (int j = 0; j < 4; j++) bvv[j] = bias[nb + tn + 16 * j];
#pragma unroll
    for (int i = 0; i < 8; i++) {
        int m = mb + tm + 16 * i;
#pragma unroll
        for (int j = 0; j < 4; j++) {
            int n = nb + tn + 16 * j;
            g_xw[(size_t)m * G3 + n] = unpack_sum(acc[i][j]) + bvv[j];
        }
    }
}

// ---------------------------------------------------------------------------
// Kernel 2: one GRU step (512 launches).
// Grid 128 CTAs x 128 threads. CTA: 8 h-columns x 3 gates x 64 batches.
// Thread: 4 batches x 3 gates = 12 packed accumulators.
// W slice (24x1024, 96KB, pitch 514 doubles) preloaded once per step.
// h(t-1) tiles (64 k-floats) double-buffered via cp.async, XOR-swizzled.
// ---------------------------------------------------------------------------
#define WS_STRIDE 514      // doubles per W row (4112B: conflict-free, 16B-aligned)
#define WS_TOTAL  (24 * WS_STRIDE)
#define HS_TILE   (64 * 32)   // doubles per h buffer (pitch 32 = 256B)

__global__ __launch_bounds__(128) void gru_step(const float* __restrict__ Whh,
                                                const float* __restrict__ bhh,
                                                const float* __restrict__ mix,
                                                float* __restrict__ out,
                                                int t) {
    extern __shared__ double sm[];
    double* ws = sm;                       // [24][514]
    double* hbuf0 = sm + WS_TOTAL;
    double* hbuf1 = sm + WS_TOTAL + HS_TILE;

    const int tid = threadIdx.x;
    const int jb = blockIdx.x * 8;
    const int jg = tid & 7;
    const int bg = tid >> 3;               // 0..15
    const int b0 = bg * 4;
    const size_t TH = (size_t)Tz * Hz;

    unsigned long long acc[4][3];
#pragma unroll
    for (int i = 0; i < 4; i++)
#pragma unroll
        for (int g = 0; g < 3; g++) acc[i][g] = 0ULL;

    if (t > 0) {
        // --- preload W slice: 24 rows x 1024 floats (48 chunks/thread) ---
#pragma unroll
        for (int c = 0; c < 48; c++) {
            int id = tid + 128 * c;        // 0..6143
            int row = id >> 8;             // 0..23
            int off = id & 255;            // 16B chunk within row
            int g = row >> 3, jj = row & 7;
            __pipeline_memcpy_async(
                (char*)(ws + (size_t)row * WS_STRIDE) + off * 16,
                &Whh[(size_t)(g * Hz + jb + jj) * Hz + off * 4], 16);
        }
        // --- h tile loader: block of 64 k-floats, all 64 batches ---
        auto load_h = [&](int kb, double* dst) {
#pragma unroll
            for (int c = 0; c < 8; c++) {
                int id = tid + 128 * c;    // 0..1023
                int row = id >> 4;         // batch 0..63
                int off = id & 15;         // 16B chunk (16 per 256B row)
                int pos = off ^ ((row >> 2) & 15);
                __pipeline_memcpy_async(
                    (char*)(dst + (size_t)row * 32) + pos * 16,
                    &out[(size_t)row * TH + (size_t)(t - 1) * Hz + kb + off * 4],
                    16);
            }
            __pipeline_commit();
        };
        load_h(0, hbuf0);       // group also flushes the W copies
        load_h(64, hbuf1);

        for (int it = 0; it < 16; ++it) {
            if (it < 14) __pipeline_wait_prior(1);
            else         __pipeline_wait_prior(0);
            __syncthreads();
            const double* H = (it & 1) ? hbuf1 : hbuf0;
            const int kofs = it * 32;
#pragma unroll
            for (int kp2 = 0; kp2 < 16; ++kp2) {
                ulonglong2 hv[4], wv[3];
#pragma unroll
                for (int i = 0; i < 4; i++) {
                    int b = b0 + i;
                    int pos = kp2 ^ ((b >> 2) & 15);
                    hv[i] = *(const ulonglong2*)&H[b * 32 + pos * 2];
                }
#pragma unroll
                for (int g = 0; g < 3; g++)
                    wv[g] = *(const ulonglong2*)&ws[(g * 8 + jg) * WS_STRIDE +
                                                    kofs + kp2 * 2];
#pragma unroll
                for (int i = 0; i < 4; i++)
#pragma unroll
                    for (int g = 0; g < 3; g++) {
                        acc[i][g] = ffma2(hv[i].x, wv[g].x, acc[i][g]);
                        acc[i][g] = ffma2(hv[i].y, wv[g].y, acc[i][g]);
                    }
            }
            __syncthreads();
            if (it + 2 < 16) load_h((it + 2) * 64, (it & 1) ? hbuf1 : hbuf0);
        }
    }

    // ---- epilogue: gates + skip-mix for 4 batches ----
    const int j = jb + jg;
    const float br = bhh[j];
    const float bz = bhh[Hz + j];
    const float bn = bhh[2 * Hz + j];

#pragma unroll
    for (int i = 0; i < 4; i++) {
        int b = b0 + i;
        float hr = unpack_sum(acc[i][0]) + br;
        float hz = unpack_sum(acc[i][1]) + bz;
        float hn = unpack_sum(acc[i][2]) + bn;

        size_t xb = ((size_t)b * Tz + t) * G3 + j;
        float xr = g_xw[xb];
        float xz = g_xw[xb + Hz];
        float xn = g_xw[xb + 2 * Hz];

        float r = 1.0f / (1.0f + expf(-(xr + hr)));
        float z = 1.0f / (1.0f + expf(-(xz + hz)));
        float n = tanhf(xn + r * hn);

        float hp = (t == 0) ? 0.0f
                            : out[(size_t)b * TH + (size_t)(t - 1) * Hz + j];
        float hnew = (1.0f - z) * n + z * hp;
        float m = mix[b * Tz + t];
        float hm = hnew * m + hp * (1.0f - m);

        out[(size_t)b * TH + (size_t)t * Hz + j] = hm;
        if (t == Tz - 1) {
            out[(size_t)Bz * TH + (size_t)b * Hz + j] = hm;   // final carry 'o'
        }
    }
}

// ---------------------------------------------------------------------------
extern "C" void kernel_launch(void* const* d_in, const int* in_sizes, int n_in,
                              void* d_out, int out_size) {
    const float* x   = (const float*)d_in[0];
    const float* mix = (const float*)d_in[1];
    const float* Wih = (const float*)d_in[2];
    const float* Whh = (const float*)d_in[3];
    const float* bih = (const float*)d_in[4];
    const float* bhh = (const float*)d_in[5];
    float* out = (float*)d_out;

    const size_t gru_smem = (WS_TOTAL + 2 * HS_TILE) * sizeof(double);
    cudaFuncSetAttribute(gru_step, cudaFuncAttributeMaxDynamicSharedMemorySize,
                         (int)gru_smem);

    dim3 ggrid(G3 / 64, Mz / 128);    // 48 x 256
    gemm_xw<<<ggrid, 256>>>(x, Wih, bih);

    for (int t = 0; t < Tz; t++) {
        gru_step<<<Hz / 8, 128, gru_smem>>>(Whh, bhh, mix, out, t);
    }
}